// round 14
// baseline (speedup 1.0000x reference)
#include <cuda_runtime.h>
#include <cstdint>

#define NB 16
#define NO 64
#define LOCS 1024
#define KVOL 576                 // 64 ch * 3 * 3
#define NSTG 4                   // W stages: 576B (144 floats) per row each

#define SMEM_B_BYTES (288 * 16 * 8)           // 36864: B tf32 slots, swizzled
#define SMEM_W_SLOT  (64 * 576)               // 36864: 64 rows x 576B
#define SMEM_W_BYTES (2 * SMEM_W_SLOT)        // 73728: 2-slot CTA-level ring
#define SMEM_TOTAL   (SMEM_B_BYTES + SMEM_W_BYTES)   // 110592 -> 2 CTAs/SM

__device__ float g_xT[64 * 32 * 32 * NB];          // (c,h,w,b), 4 MB
__device__ float g_ps[64 * NO], g_ps2[64 * NO];    // bucketed BN partials
__device__ float g_scale[NO], g_shift[NO];

__device__ __forceinline__ uint32_t tf32_rna(float f) {
    uint32_t u;
    asm("cvt.rna.tf32.f32 %0, %1;" : "=r"(u) : "f"(f));
    return u;
}
__device__ __forceinline__ void mma_tf32(float* d, const uint32_t* a, uint32_t b0,
                                         uint32_t b1) {
    asm volatile(
        "mma.sync.aligned.m16n8k8.row.col.f32.tf32.tf32.f32 "
        "{%0,%1,%2,%3}, {%4,%5,%6,%7}, {%8,%9}, {%0,%1,%2,%3};"
        : "+f"(d[0]), "+f"(d[1]), "+f"(d[2]), "+f"(d[3])
        : "r"(a[0]), "r"(a[1]), "r"(a[2]), "r"(a[3]), "r"(b0), "r"(b1));
}
__device__ __forceinline__ void cp16(void* dst_smem, const void* src) {
    unsigned d = (unsigned)__cvta_generic_to_shared(dst_smem);
    asm volatile("cp.async.ca.shared.global [%0], [%1], 16;" :: "r"(d), "l"(src));
}
#define CP_COMMIT() asm volatile("cp.async.commit_group;")
#define CP_WAIT1()  asm volatile("cp.async.wait_group 1;")

// ---------------------------------------------------------------------------
// x (b,c,h,w) -> xT (c,h,w,b); first 16 blocks also zero the BN partials.
// ---------------------------------------------------------------------------
__global__ __launch_bounds__(256) void transpose_kernel(const float* __restrict__ x) {
    int idx = blockIdx.x * 256 + threadIdx.x;
    if (blockIdx.x < 16) { g_ps[idx] = 0.f; g_ps2[idx] = 0.f; }
    int b = idx & 15, w = (idx >> 4) & 31, h = (idx >> 9) & 31, c = idx >> 14;
    g_xT[idx] = x[(((b << 6) + c) << 10) + (h << 5) + w];
}

// ---------------------------------------------------------------------------
// One CTA (256 thr, 8 warps) per output location.
// D[64 x 16] = W_loc[64 x 576] * X_loc[576 x 16], mma.sync tf32 (operands
// single tf32-RNA; rel err ~3e-4 < 1e-3).
//
// Warp m=wid&3 owns o-rows 16m..16m+15; nt=wid>>2 selects batch-tile (b 0-7
// or 8-15). W ring is CTA-level: 2 slots x 64 rows x 576B; stage st holds
// CONTIGUOUS gmem k-range [st*144, st*144+144) floats of every row -> fill
// thread t streams 144B sequential (row t>>2, quarter t&3), consecutive
// lanes cover full 576B rows (vs 256B scattered in R12).
// Slot row r at byte r*576 (odd multiple of 64 -> LDS.128 consume pattern
// (4g+tg) mod 8 bijective per 8-lane phase: conflict-free, no XOR).
// B slot (kpair kp, col n): 8B at 8*(kp*16 + ((n+2kp)&15)); consume phase
// index 4tg+g bijective -> conflict-free LDS.64.
// k convention (validated R7+): stage st, kbl, tg -> k = 16*(9st+kbl)+4tg+..,
// kp = kb*8+2tg+s pairs (2kp,2kp+1).
// ---------------------------------------------------------------------------
__global__ __launch_bounds__(256, 2) void conv_mma_kernel(const float* __restrict__ wgt,
                                                          const float* __restrict__ bias,
                                                          float* __restrict__ out) {
    extern __shared__ uint32_t bsm[];                // B fragments (36864 B)
    char* wsm = (char*)bsm + SMEM_B_BYTES;           // W ring (2 x 36864 B)
    const int tid = threadIdx.x, wid = tid >> 5, lane = tid & 31;
    const int tg = lane & 3, g = lane >> 2;
    const int m = wid & 3, nt = wid >> 2;
    const int loc = blockIdx.x, li = loc >> 5, lj = loc & 31;

    // Fill geometry: thread t -> global row o = t>>2, quarter q = t&3.
    const int frow = tid >> 2, fq = tid & 3;
    const float* fsrc = wgt + ((size_t)(frow << 10) + loc) * KVOL + fq * 36;
    char* fdst = wsm + frow * 576 + fq * 144;

#define FILL_STAGE(st, ss)                                                     \
    _Pragma("unroll")                                                          \
    for (int i = 0; i < 9; i++)                                                \
        cp16(fdst + (ss) * SMEM_W_SLOT + i * 16, fsrc + (st) * 144 + i * 4);

    FILL_STAGE(0, 0); CP_COMMIT();
    FILL_STAGE(1, 1); CP_COMMIT();

    // ---- Stage B = X tf32 fragments (swizzled stride-16 slots) ----
    for (int t = tid; t < 288 * 4; t += 256) {
        int kp = t >> 2, nq = t & 3;                 // kpair, n-quad
        float4 xq[2];
#pragma unroll
        for (int h = 0; h < 2; h++) {
            int k = 2 * kp + h;
            int c = k / 9, r = k - c * 9, p = r / 3, q = r - p * 3;
            int ih = li + p - 1, iw = lj + q - 1;
            xq[h] = make_float4(0.f, 0.f, 0.f, 0.f);
            if ((unsigned)ih < 32u && (unsigned)iw < 32u)
                xq[h] = *(const float4*)&g_xT[(((((c << 5) + ih) << 5) + iw) << 4) + (nq << 2)];
        }
        const float* x0 = &xq[0].x;
        const float* x1 = &xq[1].x;
#pragma unroll
        for (int e = 0; e < 4; e++) {
            int n = (nq << 2) + e;
            uint32_t idx = ((uint32_t)(kp << 4) + (uint32_t)((n + 2 * kp) & 15)) << 1;
            bsm[idx] = tf32_rna(x0[e]);
            bsm[idx + 1] = tf32_rna(x1[e]);
        }
    }
    __syncthreads();

    // ---- Main loop: 4 stages x 9 kb ----
    float d[4] = {0.f, 0.f, 0.f, 0.f};
    const int r0 = (m << 4) + g, r1 = r0 + 8;        // this warp's fragment rows

    for (int st = 0; st < NSTG; st++) {
        CP_WAIT1();
        __syncthreads();                              // all threads' fills visible
        const char* ap = wsm + (st & 1) * SMEM_W_SLOT + tg * 16;
#pragma unroll
        for (int kbl = 0; kbl < 9; kbl++) {
            float4 A0 = *(const float4*)(ap + r0 * 576 + kbl * 64);
            float4 A1 = *(const float4*)(ap + r1 * 576 + kbl * 64);
            int kb = st * 9 + kbl;
#pragma unroll
            for (int s = 0; s < 2; s++) {
                uint32_t aa[4];
                aa[0] = tf32_rna(s ? A0.z : A0.x);
                aa[1] = tf32_rna(s ? A1.z : A1.x);
                aa[2] = tf32_rna(s ? A0.w : A0.y);
                aa[3] = tf32_rna(s ? A1.w : A1.y);
                int kp = (kb << 3) + (tg << 1) + s;
                int n = g + (nt << 3);
                uint2 q = *(const uint2*)&bsm[((uint32_t)(kp << 4)
                              + (uint32_t)((n + 2 * kp) & 15)) << 1];
                mma_tf32(d, aa, q.x, q.y);
            }
        }
        __syncthreads();                              // slot fully consumed
        if (st + 2 < NSTG) { FILL_STAGE(st + 2, st & 1); }
        CP_COMMIT();                                  // uniform group per stage
    }

    // ---- Epilogue: lane (g,tg) holds rows o0=16m+g, o1=o0+8;
    //      cols b = 8nt + 2tg + {0,1}. ----
    int o0 = r0, o1 = r1;
    float bv0 = bias[(o0 << 10) + loc];
    float bv1 = bias[(o1 << 10) + loc];
    float s0 = 0.f, q0 = 0.f, s1 = 0.f, q1 = 0.f;
#pragma unroll
    for (int e = 0; e < 2; e++) {
        int b = (nt << 3) + (tg << 1) + e;
        float v0 = d[e] + bv0;
        float v1 = d[e + 2] + bv1;
        out[(((b << 6) + o0) << 10) + loc] = v0;
        out[(((b << 6) + o1) << 10) + loc] = v1;
        s0 += v0; q0 = fmaf(v0, v0, q0);
        s1 += v1; q1 = fmaf(v1, v1, q1);
    }
#pragma unroll
    for (int mm = 1; mm < 4; mm <<= 1) {
        s0 += __shfl_down_sync(0xffffffffu, s0, mm, 4);
        q0 += __shfl_down_sync(0xffffffffu, q0, mm, 4);
        s1 += __shfl_down_sync(0xffffffffu, s1, mm, 4);
        q1 += __shfl_down_sync(0xffffffffu, q1, mm, 4);
    }
    if (tg == 0) {
        int bkt = loc & 63;
        atomicAdd(&g_ps[(bkt << 6) + o0], s0);
        atomicAdd(&g_ps2[(bkt << 6) + o0], q0);
        atomicAdd(&g_ps[(bkt << 6) + o1], s1);
        atomicAdd(&g_ps2[(bkt << 6) + o1], q1);
    }
}

// ---------------------------------------------------------------------------
__global__ void params_kernel(const float* __restrict__ gamma,
                              const float* __restrict__ beta) {
    int o = threadIdx.x;
    float S = 0.f, S2 = 0.f;
    for (int k = 0; k < 64; k++) { S += g_ps[(k << 6) + o]; S2 += g_ps2[(k << 6) + o]; }
    const float inv = 1.f / (float)(NB * LOCS);
    float mean = S * inv;
    float var = S2 * inv - mean * mean;              // biased variance (ddof=0)
    float sc = gamma[o] * rsqrtf(var + 1e-5f);
    g_scale[o] = sc;
    g_shift[o] = beta[o] - mean * sc;
}

__global__ __launch_bounds__(256) void finalize_kernel(float* __restrict__ y) {
    int idx = blockIdx.x * 256 + threadIdx.x;
    int o = (idx >> 8) & 63;
    float sc = g_scale[o], sh = g_shift[o];
    float4 v = ((float4*)y)[idx];
    v.x = fmaxf(fmaf(v.x, sc, sh), 0.f);
    v.y = fmaxf(fmaf(v.y, sc, sh), 0.f);
    v.z = fmaxf(fmaf(v.z, sc, sh), 0.f);
    v.w = fmaxf(fmaf(v.w, sc, sh), 0.f);
    ((float4*)y)[idx] = v;
}

extern "C" void kernel_launch(void* const* d_in, const int* in_sizes, int n_in,
                              void* d_out, int out_size) {
    const float* x     = (const float*)d_in[0];
    const float* w     = (const float*)d_in[1];
    const float* bias  = (const float*)d_in[2];
    const float* gamma = (const float*)d_in[3];
    const float* beta  = (const float*)d_in[4];
    float* out = (float*)d_out;

    cudaFuncSetAttribute(conv_mma_kernel, cudaFuncAttributeMaxDynamicSharedMemorySize,
                         SMEM_TOTAL);

    transpose_kernel<<<4096, 256>>>(x);                  // + zero BN partials
    conv_mma_kernel<<<1024, 256, SMEM_TOTAL>>>(w, bias, out);
    params_kernel<<<1, 64>>>(gamma, beta);
    finalize_kernel<<<1024, 256>>>(out);
}

// round 15
// speedup vs baseline: 1.6274x; 1.6274x over previous
#include <cuda_runtime.h>
#include <cstdint>

#define NB 16
#define NO 64
#define LOCS 1024
#define KVOL 576                 // 64 ch * 3 * 3
#define RSF (LOCS * KVOL)        // row stride in floats between o-rows

#define SMEM_B_BYTES (288 * 16 * 8)     // 36864: B tf32 slots (stride-16, swizzled)
#define SMEM_W_BYTES (4 * 2 * 8192)     // 65536: 4 warps x 2 slots x 8KB
#define SMEM_TOTAL   (SMEM_B_BYTES + SMEM_W_BYTES)   // 102400 -> 2 CTAs/SM

__device__ float g_xT[64 * 32 * 32 * NB];          // (c,h,w,b), 4 MB
__device__ float g_ps[64 * NO], g_ps2[64 * NO];    // bucketed BN partials
__device__ float g_scale[NO], g_shift[NO];

__device__ __forceinline__ uint32_t tf32_rna(float f) {
    uint32_t u;
    asm("cvt.rna.tf32.f32 %0, %1;" : "=r"(u) : "f"(f));
    return u;
}
__device__ __forceinline__ void mma_tf32(float* d, const uint32_t* a, uint32_t b0,
                                         uint32_t b1) {
    asm volatile(
        "mma.sync.aligned.m16n8k8.row.col.f32.tf32.tf32.f32 "
        "{%0,%1,%2,%3}, {%4,%5,%6,%7}, {%8,%9}, {%0,%1,%2,%3};"
        : "+f"(d[0]), "+f"(d[1]), "+f"(d[2]), "+f"(d[3])
        : "r"(a[0]), "r"(a[1]), "r"(a[2]), "r"(a[3]), "r"(b0), "r"(b1));
}
__device__ __forceinline__ void cp16(void* dst_smem, const void* src) {
    unsigned d = (unsigned)__cvta_generic_to_shared(dst_smem);
    asm volatile("cp.async.ca.shared.global [%0], [%1], 16;" :: "r"(d), "l"(src));
}
#define CP_COMMIT() asm volatile("cp.async.commit_group;")
#define CP_WAIT1()  asm volatile("cp.async.wait_group 1;")

// ---------------------------------------------------------------------------
// x (b,c,h,w) -> xT (c,h,w,b); first 16 blocks also zero the BN partials.
// ---------------------------------------------------------------------------
__global__ __launch_bounds__(256) void transpose_kernel(const float* __restrict__ x) {
    int idx = blockIdx.x * 256 + threadIdx.x;
    if (blockIdx.x < 16) { g_ps[idx] = 0.f; g_ps2[idx] = 0.f; }
    int b = idx & 15, w = (idx >> 4) & 31, h = (idx >> 9) & 31, c = idx >> 14;
    g_xT[idx] = x[(((b << 6) + c) << 10) + (h << 5) + w];
}

// ---------------------------------------------------------------------------
// One CTA (128 thr, 4 warps) per output location.
// D[64 x 16] = W_loc[64 x 576] * X_loc[576 x 16], mma.sync tf32 (operands
// single tf32-RNA; rel err ~3e-4 < 1e-3).
//
// W: per-warp 2-slot ring, stage = 16 rows x 512B where EACH warp-instruction
// covers 512B CONTIGUOUS of one row (32 lanes x 16B, same row) -> maximal
// DRAM burst per request. 2304B/row = 4 full stages + 1 tail stage (256B/row,
// dual-row instructions). Slot layout: row r at r*512, 64B-block swizzle
// blk' = blk ^ (r&7): fill-STS and LDS.128-consume both conflict-free
// (adjacent-g lanes take opposite 16-bank halves via the XOR parity).
// B slot (kpair kp, col n): 8B at 8*(kp*16 + ((n+2kp)&15)) [R14-validated].
// ---------------------------------------------------------------------------
__global__ __launch_bounds__(128, 2) void conv_mma_kernel(const float* __restrict__ wgt,
                                                          const float* __restrict__ bias,
                                                          float* __restrict__ out) {
    extern __shared__ uint32_t bsm[];                // B fragments (36864 B)
    char* wsm = (char*)bsm + SMEM_B_BYTES;           // W ring
    const int tid = threadIdx.x, wid = tid >> 5, lane = tid & 31;
    const int tg = lane & 3, g = lane >> 2;
    const int loc = blockIdx.x, li = loc >> 5, lj = loc & 31;

    char* wslot = wsm + (wid << 14);                 // this warp's 2 x 8KB
    // Full-stage fill geometry: instruction r -> row r, lane L -> byte L*16.
    const float* fbase = wgt + ((size_t)(wid << 4) * LOCS + loc) * KVOL + (lane << 2);
    const int blkL = lane >> 2, wi = (lane & 3) << 4;

#define FILL_FULL(st, ss)                                                      \
    _Pragma("unroll")                                                          \
    for (int r = 0; r < 16; r++)                                               \
        cp16(wslot + ((ss) << 13) + (r << 9) + (((blkL ^ r) & 7) << 6) + wi,   \
             fbase + (size_t)r * RSF + (st) * 128);

    // Tail stage (k floats [512,576), 256B/row): instr i -> rows 2i, 2i+1.
    const int rtop = lane >> 4, l16 = lane & 15;
    const float* tbase = wgt + ((size_t)(wid << 4) * LOCS + loc) * KVOL + 512 + (l16 << 2);
    const int tblk = l16 >> 2, twi = (l16 & 3) << 4;

#define FILL_TAIL(ss)                                                          \
    _Pragma("unroll")                                                          \
    for (int i = 0; i < 8; i++) {                                              \
        int r = (i << 1) + rtop;                                               \
        cp16(wslot + ((ss) << 13) + (r << 9) + (((tblk ^ r) & 7) << 6) + twi,  \
             tbase + (size_t)r * RSF);                                         \
    }

    FILL_FULL(0, 0); CP_COMMIT();
    FILL_FULL(1, 1); CP_COMMIT();

    // ---- Stage B = X tf32 fragments (stride-16 swizzled slots) ----
    for (int t = tid; t < 288 * 4; t += 128) {
        int kp = t >> 2, nq = t & 3;                 // kpair, n-quad
        float4 xq[2];
#pragma unroll
        for (int h = 0; h < 2; h++) {
            int k = 2 * kp + h;
            int c = k / 9, r = k - c * 9, p = r / 3, q = r - p * 3;
            int ih = li + p - 1, iw = lj + q - 1;
            xq[h] = make_float4(0.f, 0.f, 0.f, 0.f);
            if ((unsigned)ih < 32u && (unsigned)iw < 32u)
                xq[h] = *(const float4*)&g_xT[(((((c << 5) + ih) << 5) + iw) << 4) + (nq << 2)];
        }
        const float* x0 = &xq[0].x;
        const float* x1 = &xq[1].x;
#pragma unroll
        for (int e = 0; e < 4; e++) {
            int n = (nq << 2) + e;
            uint32_t idx = ((uint32_t)(kp << 4) + (uint32_t)((n + 2 * kp) & 15)) << 1;
            bsm[idx] = tf32_rna(x0[e]);
            bsm[idx + 1] = tf32_rna(x1[e]);
        }
    }
    __syncthreads();

    // ---- Main loop: 4 full stages x 8 kb, then tail stage x 4 kb ----
    float d[2][4] = {{0.f, 0.f, 0.f, 0.f}, {0.f, 0.f, 0.f, 0.f}};

#define DO_KB(ap, kb, kbl)                                                     \
    {                                                                          \
        int sw = ((kbl) ^ g) & 7;                                              \
        float4 A0 = *(const float4*)((ap) + (g << 9) + (sw << 6) + (tg << 4)); \
        float4 A1 = *(const float4*)((ap) + ((g + 8) << 9) + (sw << 6) + (tg << 4)); \
        _Pragma("unroll")                                                      \
        for (int s = 0; s < 2; s++) {                                          \
            uint32_t aa[4];                                                    \
            aa[0] = tf32_rna(s ? A0.z : A0.x);                                 \
            aa[1] = tf32_rna(s ? A1.z : A1.x);                                 \
            aa[2] = tf32_rna(s ? A0.w : A0.y);                                 \
            aa[3] = tf32_rna(s ? A1.w : A1.y);                                 \
            int kp = ((kb) << 3) + (tg << 1) + s;                              \
            _Pragma("unroll")                                                  \
            for (int nt = 0; nt < 2; nt++) {                                   \
                int n = g + (nt << 3);                                         \
                uint2 q = *(const uint2*)&bsm[((uint32_t)(kp << 4)             \
                              + (uint32_t)((n + 2 * kp) & 15)) << 1];          \
                mma_tf32(d[nt], aa, q.x, q.y);                                 \
            }                                                                  \
        }                                                                      \
    }

    for (int st = 0; st < 4; st++) {
        CP_WAIT1();
        __syncwarp();
        const char* ap = wslot + ((st & 1) << 13);
#pragma unroll
        for (int kbl = 0; kbl < 8; kbl++) DO_KB(ap, st * 8 + kbl, kbl)
        __syncwarp();
        if (st < 2) { FILL_FULL(st + 2, st & 1); }
        else if (st == 2) { FILL_TAIL(0); }
        CP_COMMIT();
    }
    {   // tail stage: slot 0, kb 32..35
        CP_WAIT1();
        __syncwarp();
        const char* ap = wslot;
#pragma unroll
        for (int kbl = 0; kbl < 4; kbl++) DO_KB(ap, 32 + kbl, kbl)
    }

    // ---- Epilogue: lane (g,tg) holds rows o0=16wid+g, o1=o0+8;
    //      cols b = 8nt + 2tg + {0,1}. ----
    int o0 = (wid << 4) + g, o1 = o0 + 8;
    float bv0 = bias[(o0 << 10) + loc];
    float bv1 = bias[(o1 << 10) + loc];
    float s0 = 0.f, q0 = 0.f, s1 = 0.f, q1 = 0.f;
#pragma unroll
    for (int nt = 0; nt < 2; nt++) {
#pragma unroll
        for (int e = 0; e < 2; e++) {
            int b = (nt << 3) + (tg << 1) + e;
            float v0 = d[nt][e] + bv0;
            float v1 = d[nt][e + 2] + bv1;
            out[(((b << 6) + o0) << 10) + loc] = v0;
            out[(((b << 6) + o1) << 10) + loc] = v1;
            s0 += v0; q0 = fmaf(v0, v0, q0);
            s1 += v1; q1 = fmaf(v1, v1, q1);
        }
    }
#pragma unroll
    for (int m = 1; m < 4; m <<= 1) {
        s0 += __shfl_down_sync(0xffffffffu, s0, m, 4);
        q0 += __shfl_down_sync(0xffffffffu, q0, m, 4);
        s1 += __shfl_down_sync(0xffffffffu, s1, m, 4);
        q1 += __shfl_down_sync(0xffffffffu, q1, m, 4);
    }
    if (tg == 0) {
        int bkt = loc & 63;
        atomicAdd(&g_ps[(bkt << 6) + o0], s0);
        atomicAdd(&g_ps2[(bkt << 6) + o0], q0);
        atomicAdd(&g_ps[(bkt << 6) + o1], s1);
        atomicAdd(&g_ps2[(bkt << 6) + o1], q1);
    }
}

// ---------------------------------------------------------------------------
__global__ void params_kernel(const float* __restrict__ gamma,
                              const float* __restrict__ beta) {
    int o = threadIdx.x;
    float S = 0.f, S2 = 0.f;
    for (int k = 0; k < 64; k++) { S += g_ps[(k << 6) + o]; S2 += g_ps2[(k << 6) + o]; }
    const float inv = 1.f / (float)(NB * LOCS);
    float mean = S * inv;
    float var = S2 * inv - mean * mean;              // biased variance (ddof=0)
    float sc = gamma[o] * rsqrtf(var + 1e-5f);
    g_scale[o] = sc;
    g_shift[o] = beta[o] - mean * sc;
}

__global__ __launch_bounds__(256) void finalize_kernel(float* __restrict__ y) {
    int idx = blockIdx.x * 256 + threadIdx.x;
    int o = (idx >> 8) & 63;
    float sc = g_scale[o], sh = g_shift[o];
    float4 v = ((float4*)y)[idx];
    v.x = fmaxf(fmaf(v.x, sc, sh), 0.f);
    v.y = fmaxf(fmaf(v.y, sc, sh), 0.f);
    v.z = fmaxf(fmaf(v.z, sc, sh), 0.f);
    v.w = fmaxf(fmaf(v.w, sc, sh), 0.f);
    ((float4*)y)[idx] = v;
}

extern "C" void kernel_launch(void* const* d_in, const int* in_sizes, int n_in,
                              void* d_out, int out_size) {
    const float* x     = (const float*)d_in[0];
    const float* w     = (const float*)d_in[1];
    const float* bias  = (const float*)d_in[2];
    const float* gamma = (const float*)d_in[3];
    const float* beta  = (const float*)d_in[4];
    float* out = (float*)d_out;

    cudaFuncSetAttribute(conv_mma_kernel, cudaFuncAttributeMaxDynamicSharedMemorySize,
                         SMEM_TOTAL);

    transpose_kernel<<<4096, 256>>>(x);                  // + zero BN partials
    conv_mma_kernel<<<1024, 128, SMEM_TOTAL>>>(w, bias, out);
    params_kernel<<<1, 64>>>(gamma, beta);
    finalize_kernel<<<1024, 256>>>(out);
}